// round 1
// baseline (speedup 1.0000x reference)
#include <cuda_runtime.h>

// ---------------------------------------------------------------------------
// Problem constants (shapes fixed by the dataset; sizes derived at launch)
// ---------------------------------------------------------------------------
#define NT_MAX 200000

// Scratch (allocation-free rule: __device__ globals)
__device__ float g_agg  [NT_MAX * 5];
__device__ float g_fused[NT_MAX * 64];
__device__ float g_Bdep [NT_MAX * 64];
__device__ float g_Cdep [NT_MAX * 64];
__device__ float g_Brev [NT_MAX * 64];
__device__ float g_Crev [NT_MAX * 64];
__device__ float g_Sdep [NT_MAX * 64];
__device__ float g_Srev [NT_MAX * 64];
__device__ int   g_degD [NT_MAX];
__device__ int   g_degR [NT_MAX];
__device__ float g_colsum[64];

__device__ __forceinline__ float leaky(float x) { return x > 0.f ? x : 0.01f * x; }

__device__ __forceinline__ float warp_sum(float v) {
#pragma unroll
    for (int o = 16; o > 0; o >>= 1) v += __shfl_xor_sync(0xffffffffu, v, o);
    return v;
}

// ---------------------------------------------------------------------------
// K0: zero all accumulators
// ---------------------------------------------------------------------------
__global__ void k_zero(int n) {
    int i = blockIdx.x * blockDim.x + threadIdx.x;
    int m4 = n * 16;  // n*64 floats / 4
    float4 z = make_float4(0.f, 0.f, 0.f, 0.f);
    if (i < m4) {
        reinterpret_cast<float4*>(g_Sdep)[i] = z;
        reinterpret_cast<float4*>(g_Srev)[i] = z;
    }
    if (i < n * 5) g_agg[i] = 0.f;
    if (i < n) { g_degD[i] = 0; g_degR[i] = 0; }
    if (i < 64) g_colsum[i] = 0.f;
}

// ---------------------------------------------------------------------------
// K1: data->task scatter-add (GraphConv aggregation)
// ---------------------------------------------------------------------------
__global__ void k_dt(const float* __restrict__ data_x,
                     const int* __restrict__ src, const int* __restrict__ dst, int E) {
    int e = blockIdx.x * blockDim.x + threadIdx.x;
    if (e >= E) return;
    int s = __ldg(&src[e]);
    int d = __ldg(&dst[e]);
    const float* xr = data_x + s * 5;
    float* ar = g_agg + d * 5;
#pragma unroll
    for (int k = 0; k < 5; k++) atomicAdd(ar + k, __ldg(&xr[k]));
}

// ---------------------------------------------------------------------------
// K2: fused = leaky(LN(agg @ Wrel + brel + tasks @ Wroot))   (warp per row)
// ---------------------------------------------------------------------------
__global__ void k_fused(const float* __restrict__ tasks_x,
                        const float* __restrict__ Wrel, const float* __restrict__ brel,
                        const float* __restrict__ Wroot,
                        const float* __restrict__ lng, const float* __restrict__ lnb,
                        int n) {
    int gt = blockIdx.x * blockDim.x + threadIdx.x;
    int r = gt >> 5, lane = gt & 31;
    if (r >= n) return;
    float p0 = __ldg(&brel[lane]);
    float p1 = __ldg(&brel[lane + 32]);
    const float* ar = g_agg + r * 5;
#pragma unroll
    for (int k = 0; k < 5; k++) {
        float a = ar[k];
        p0 += a * __ldg(&Wrel[k * 64 + lane]);
        p1 += a * __ldg(&Wrel[k * 64 + lane + 32]);
    }
    const float* tr = tasks_x + r * 12;
#pragma unroll
    for (int k = 0; k < 12; k++) {
        float t = __ldg(&tr[k]);
        p0 += t * __ldg(&Wroot[k * 64 + lane]);
        p1 += t * __ldg(&Wroot[k * 64 + lane + 32]);
    }
    float m = warp_sum(p0 + p1) * (1.f / 64.f);
    float d0 = p0 - m, d1 = p1 - m;
    float v = warp_sum(d0 * d0 + d1 * d1) * (1.f / 64.f);
    float inv = rsqrtf(v + 1e-5f);
    float y0 = leaky(d0 * inv * __ldg(&lng[lane])      + __ldg(&lnb[lane]));
    float y1 = leaky(d1 * inv * __ldg(&lng[lane + 32]) + __ldg(&lnb[lane + 32]));
    g_fused[r * 64 + lane]      = y0;
    g_fused[r * 64 + lane + 32] = y1;
}

// ---------------------------------------------------------------------------
// K3: B = fused @ W1b, C = fused @ (W1a - W1b) for one conv
//     Tile: 128 rows x 128 cols (cols 0..63 -> B, 64..127 -> C), 256 threads
// ---------------------------------------------------------------------------
__global__ __launch_bounds__(256) void k_gemm_bc(const float* __restrict__ W1,
                                                 int n, int conv) {
    extern __shared__ float sm[];
    float* Ws = sm;            // [64][128] = 8192
    float* Xs = sm + 8192;     // [128][65] = 8320
    int tid = threadIdx.x;
    int row0 = blockIdx.x * 128;

    // Ws[k][j]: j<64 -> W1b[k][j] = W1[(64+k)*64+j]; j>=64 -> W1a-W1b
    for (int idx = tid; idx < 8192; idx += 256) {
        int k = idx >> 7, j = idx & 127;
        float wB = W1[(64 + k) * 64 + (j & 63)];
        Ws[idx] = (j < 64) ? wB : (W1[k * 64 + (j - 64)] - wB);
    }
    // Xs: 128x64 tile of g_fused (padded stride 65), OOB rows zero
#pragma unroll
    for (int it = 0; it < 8; it++) {
        int fi = tid + it * 256;            // 0..2047 float4 slots
        int r = fi >> 4, c4 = (fi & 15) * 4;
        float4 v = make_float4(0.f, 0.f, 0.f, 0.f);
        int row = row0 + r;
        if (row < n) v = *reinterpret_cast<const float4*>(&g_fused[row * 64 + c4]);
        Xs[r * 65 + c4 + 0] = v.x;
        Xs[r * 65 + c4 + 1] = v.y;
        Xs[r * 65 + c4 + 2] = v.z;
        Xs[r * 65 + c4 + 3] = v.w;
    }
    __syncthreads();

    int tr = tid >> 4;   // 0..15 -> 8 rows each
    int tc = tid & 15;   // 0..15 -> 8 cols each
    float acc[8][8];
#pragma unroll
    for (int i = 0; i < 8; i++)
#pragma unroll
        for (int j = 0; j < 8; j++) acc[i][j] = 0.f;

#pragma unroll 4
    for (int k = 0; k < 64; k++) {
        float4 w0 = *reinterpret_cast<float4*>(&Ws[k * 128 + tc * 8]);
        float4 w1 = *reinterpret_cast<float4*>(&Ws[k * 128 + tc * 8 + 4]);
#pragma unroll
        for (int i = 0; i < 8; i++) {
            float x = Xs[(tr * 8 + i) * 65 + k];
            acc[i][0] += x * w0.x; acc[i][1] += x * w0.y;
            acc[i][2] += x * w0.z; acc[i][3] += x * w0.w;
            acc[i][4] += x * w1.x; acc[i][5] += x * w1.y;
            acc[i][6] += x * w1.z; acc[i][7] += x * w1.w;
        }
    }

    float* Bo = conv ? g_Brev : g_Bdep;
    float* Co = conv ? g_Crev : g_Cdep;
    float* O = (tc < 8) ? Bo : Co;
    int cbase = (tc < 8) ? tc * 8 : (tc - 8) * 8;
#pragma unroll
    for (int i = 0; i < 8; i++) {
        int row = row0 + tr * 8 + i;
        if (row < n) {
            *reinterpret_cast<float4*>(&O[row * 64 + cbase]) =
                make_float4(acc[i][0], acc[i][1], acc[i][2], acc[i][3]);
            *reinterpret_cast<float4*>(&O[row * 64 + cbase + 4]) =
                make_float4(acc[i][4], acc[i][5], acc[i][6], acc[i][7]);
        }
    }
}

// ---------------------------------------------------------------------------
// K4: edge pass. For each edge: S[dst] += leaky(C[dst] + B[src] + b1), deg[dst]++
//     16 threads per edge, float4 per thread
// ---------------------------------------------------------------------------
__global__ __launch_bounds__(256) void k_edge(const int* __restrict__ esrc,
                                              const int* __restrict__ edst,
                                              const float* __restrict__ b1,
                                              int E, int conv) {
    int t = blockIdx.x * blockDim.x + threadIdx.x;
    int e = t >> 4;
    if (e >= E) return;
    int c = (t & 15) * 4;
    int s = __ldg(&esrc[e]);
    int d = __ldg(&edst[e]);
    const float* B = conv ? g_Brev : g_Bdep;
    const float* C = conv ? g_Crev : g_Cdep;
    float* S = conv ? g_Srev : g_Sdep;
    float4 cv = *reinterpret_cast<const float4*>(&C[d * 64 + c]);
    float4 bv = *reinterpret_cast<const float4*>(&B[s * 64 + c]);
    float4 bb = *reinterpret_cast<const float4*>(&b1[c]);
    float v0 = leaky(cv.x + bv.x + bb.x);
    float v1 = leaky(cv.y + bv.y + bb.y);
    float v2 = leaky(cv.z + bv.z + bb.z);
    float v3 = leaky(cv.w + bv.w + bb.w);
    float* sp = S + d * 64 + c;
    atomicAdd(sp + 0, v0);
    atomicAdd(sp + 1, v1);
    atomicAdd(sp + 2, v2);
    atomicAdd(sp + 3, v3);
    if ((t & 15) == 0) {
        int* deg = conv ? g_degR : g_degD;
        atomicAdd(&deg[d], 1);
    }
}

// ---------------------------------------------------------------------------
// K5: per-node tail: dep = leaky(LN(Sdep@W2d + degD*b2d)); rev likewise;
//     tf = leaky([dep,rev]@P + pb); colsum += tf; tf[0] -> out[64..127]
//     Warp per row, shuffle-broadcast GEMMs from shared weights.
// ---------------------------------------------------------------------------
__global__ __launch_bounds__(256) void k_stage45(
    const float* __restrict__ depW2, const float* __restrict__ depb2,
    const float* __restrict__ depg,  const float* __restrict__ depb,
    const float* __restrict__ revW2, const float* __restrict__ revb2,
    const float* __restrict__ revg,  const float* __restrict__ revb,
    const float* __restrict__ projW, const float* __restrict__ projb,
    float* __restrict__ out, int n) {
    extern __shared__ float sm[];
    float* shW2d = sm;             // 4096
    float* shW2r = sm + 4096;      // 4096
    float* shP   = sm + 8192;      // 8192
    float* shS   = sm + 16384;     // 448 small vectors
    int tid = threadIdx.x;
    for (int idx = tid; idx < 4096; idx += 256) shW2d[idx] = depW2[idx];
    for (int idx = tid; idx < 4096; idx += 256) shW2r[idx] = revW2[idx];
    for (int idx = tid; idx < 8192; idx += 256) shP[idx] = projW[idx];
    if (tid < 64) {
        shS[tid]       = depb2[tid];
        shS[64 + tid]  = revb2[tid];
        shS[128 + tid] = depg[tid];
        shS[192 + tid] = depb[tid];
        shS[256 + tid] = revg[tid];
        shS[320 + tid] = revb[tid];
        shS[384 + tid] = projb[tid];
    }
    __syncthreads();

    int lane = tid & 31, wid = tid >> 5;
    float acc0 = 0.f, acc1 = 0.f;

    for (int r = blockIdx.x * 8 + wid; r < n; r += gridDim.x * 8) {
        // ---- dep branch ----
        float s0 = g_Sdep[r * 64 + lane];
        float s1 = g_Sdep[r * 64 + 32 + lane];
        float dg = (float)g_degD[r];
        float p0 = dg * shS[lane];
        float p1 = dg * shS[32 + lane];
#pragma unroll
        for (int k = 0; k < 32; k++) {
            float a = __shfl_sync(0xffffffffu, s0, k);
            p0 += a * shW2d[k * 64 + lane];
            p1 += a * shW2d[k * 64 + 32 + lane];
        }
#pragma unroll
        for (int k = 0; k < 32; k++) {
            float a = __shfl_sync(0xffffffffu, s1, k);
            p0 += a * shW2d[(k + 32) * 64 + lane];
            p1 += a * shW2d[(k + 32) * 64 + 32 + lane];
        }
        float m = warp_sum(p0 + p1) * (1.f / 64.f);
        float e0 = p0 - m, e1 = p1 - m;
        float v = warp_sum(e0 * e0 + e1 * e1) * (1.f / 64.f);
        float inv = rsqrtf(v + 1e-5f);
        float d0 = leaky(e0 * inv * shS[128 + lane] + shS[192 + lane]);
        float d1 = leaky(e1 * inv * shS[160 + lane] + shS[224 + lane]);

        // ---- rev branch ----
        s0 = g_Srev[r * 64 + lane];
        s1 = g_Srev[r * 64 + 32 + lane];
        dg = (float)g_degR[r];
        p0 = dg * shS[64 + lane];
        p1 = dg * shS[96 + lane];
#pragma unroll
        for (int k = 0; k < 32; k++) {
            float a = __shfl_sync(0xffffffffu, s0, k);
            p0 += a * shW2r[k * 64 + lane];
            p1 += a * shW2r[k * 64 + 32 + lane];
        }
#pragma unroll
        for (int k = 0; k < 32; k++) {
            float a = __shfl_sync(0xffffffffu, s1, k);
            p0 += a * shW2r[(k + 32) * 64 + lane];
            p1 += a * shW2r[(k + 32) * 64 + 32 + lane];
        }
        m = warp_sum(p0 + p1) * (1.f / 64.f);
        e0 = p0 - m; e1 = p1 - m;
        v = warp_sum(e0 * e0 + e1 * e1) * (1.f / 64.f);
        inv = rsqrtf(v + 1e-5f);
        float r0 = leaky(e0 * inv * shS[256 + lane] + shS[320 + lane]);
        float r1 = leaky(e1 * inv * shS[288 + lane] + shS[352 + lane]);

        // ---- projection ----
        float q0 = shS[384 + lane];
        float q1 = shS[416 + lane];
#pragma unroll
        for (int k = 0; k < 32; k++) {
            float a = __shfl_sync(0xffffffffu, d0, k);
            q0 += a * shP[k * 64 + lane];
            q1 += a * shP[k * 64 + 32 + lane];
        }
#pragma unroll
        for (int k = 0; k < 32; k++) {
            float a = __shfl_sync(0xffffffffu, d1, k);
            q0 += a * shP[(k + 32) * 64 + lane];
            q1 += a * shP[(k + 32) * 64 + 32 + lane];
        }
#pragma unroll
        for (int k = 0; k < 32; k++) {
            float a = __shfl_sync(0xffffffffu, r0, k);
            q0 += a * shP[(k + 64) * 64 + lane];
            q1 += a * shP[(k + 64) * 64 + 32 + lane];
        }
#pragma unroll
        for (int k = 0; k < 32; k++) {
            float a = __shfl_sync(0xffffffffu, r1, k);
            q0 += a * shP[(k + 96) * 64 + lane];
            q1 += a * shP[(k + 96) * 64 + 32 + lane];
        }
        float t0 = leaky(q0), t1 = leaky(q1);
        acc0 += t0;
        acc1 += t1;
        if (r == 0) {
            out[64 + lane] = t0;
            out[96 + lane] = t1;
        }
    }
    atomicAdd(&g_colsum[lane], acc0);
    atomicAdd(&g_colsum[lane + 32], acc1);
}

// ---------------------------------------------------------------------------
// K6: finalize global state + device branch
// ---------------------------------------------------------------------------
__global__ void k_final(const int* __restrict__ counts,
                        const float* __restrict__ devx,
                        const float* __restrict__ timex,
                        const float* __restrict__ devW,
                        const float* __restrict__ devb,
                        float* __restrict__ out) {
    int tid = threadIdx.x;
    if (tid < 64) {
        int c = counts[0];
        if (c < 1) c = 1;
        out[tid] = g_colsum[tid] / (float)c;
    } else if (tid < 128) {
        int j = tid - 64;
        float p = devb[j];
#pragma unroll 8
        for (int k = 0; k < 96; k++) p += devx[k] * devW[k * 64 + j];
        p += (timex[0] * 1e-5f) * devW[96 * 64 + j];
        out[128 + j] = leaky(p);
    }
}

// ---------------------------------------------------------------------------
// Launch
// ---------------------------------------------------------------------------
extern "C" void kernel_launch(void* const* d_in, const int* in_sizes, int n_in,
                              void* d_out, int out_size) {
    const float* data_x    = (const float*)d_in[0];
    const float* tasks_x   = (const float*)d_in[1];
    const float* devices_x = (const float*)d_in[2];
    const float* time_x    = (const float*)d_in[3];
    const int*   dt_src    = (const int*)d_in[4];
    const int*   dt_dst    = (const int*)d_in[5];
    const int*   tt_src    = (const int*)d_in[6];
    const int*   tt_dst    = (const int*)d_in[7];
    const int*   counts    = (const int*)d_in[8];
    const float* gcWrel    = (const float*)d_in[9];
    const float* gcbrel    = (const float*)d_in[10];
    const float* gcWroot   = (const float*)d_in[11];
    const float* gclng     = (const float*)d_in[12];
    const float* gclnb     = (const float*)d_in[13];
    const float* depW1     = (const float*)d_in[14];
    const float* depb1     = (const float*)d_in[15];
    const float* depW2     = (const float*)d_in[16];
    const float* depb2     = (const float*)d_in[17];
    const float* deplng    = (const float*)d_in[18];
    const float* deplnb    = (const float*)d_in[19];
    const float* revW1     = (const float*)d_in[20];
    const float* revb1     = (const float*)d_in[21];
    const float* revW2     = (const float*)d_in[22];
    const float* revb2     = (const float*)d_in[23];
    const float* revlng    = (const float*)d_in[24];
    const float* revlnb    = (const float*)d_in[25];
    const float* devW      = (const float*)d_in[26];
    const float* devb      = (const float*)d_in[27];
    const float* projW     = (const float*)d_in[28];
    const float* projb     = (const float*)d_in[29];
    float* out = (float*)d_out;

    int n    = in_sizes[1] / 12;   // tasks
    int e_dt = in_sizes[4];
    int e_tt = in_sizes[6];

    cudaFuncSetAttribute(k_gemm_bc, cudaFuncAttributeMaxDynamicSharedMemorySize, 66048);
    cudaFuncSetAttribute(k_stage45, cudaFuncAttributeMaxDynamicSharedMemorySize, 67328);

    k_zero<<<(n * 16 + 255) / 256, 256>>>(n);
    k_dt<<<(e_dt + 255) / 256, 256>>>(data_x, dt_src, dt_dst, e_dt);
    k_fused<<<(n * 32 + 255) / 256, 256>>>(tasks_x, gcWrel, gcbrel, gcWroot, gclng, gclnb, n);

    int gb = (n + 127) / 128;
    k_gemm_bc<<<gb, 256, 66048>>>(depW1, n, 0);
    k_gemm_bc<<<gb, 256, 66048>>>(revW1, n, 1);

    int eb = (e_tt * 16 + 255) / 256;
    k_edge<<<eb, 256>>>(tt_src, tt_dst, depb1, e_tt, 0);
    k_edge<<<eb, 256>>>(tt_dst, tt_src, revb1, e_tt, 1);

    k_stage45<<<1184, 256, 67328>>>(depW2, depb2, deplng, deplnb,
                                    revW2, revb2, revlng, revlnb,
                                    projW, projb, out, n);
    k_final<<<1, 128>>>(counts, devices_x, time_x, devW, devb, out);
}

// round 2
// speedup vs baseline: 1.2378x; 1.2378x over previous
#include <cuda_runtime.h>

#define NT_MAX 200000
#define ETT_MAX 1100000

// ---------------------------------------------------------------------------
// Scratch (__device__ globals — allocation-free rule)
// ---------------------------------------------------------------------------
__device__ float g_agg  [NT_MAX * 5];
__device__ float g_fused[NT_MAX * 64];
__device__ float g_Bdep [NT_MAX * 64];
__device__ float g_Cdep [NT_MAX * 64];
__device__ float g_Brev [NT_MAX * 64];
__device__ float g_Crev [NT_MAX * 64];
__device__ int   g_degD [NT_MAX];
__device__ int   g_degR [NT_MAX];
__device__ int   g_ptrD [NT_MAX + 1];
__device__ int   g_ptrR [NT_MAX + 1];
__device__ int   g_curD [NT_MAX];
__device__ int   g_curR [NT_MAX];
__device__ int   g_srcD [ETT_MAX];
__device__ int   g_srcR [ETT_MAX];
__device__ int   g_bsumD[512];
__device__ int   g_bsumR[512];
__device__ float g_colsum[64];

__device__ __forceinline__ float leaky(float x) { return x > 0.f ? x : 0.01f * x; }

__device__ __forceinline__ float warp_sum(float v) {
#pragma unroll
    for (int o = 16; o > 0; o >>= 1) v += __shfl_xor_sync(0xffffffffu, v, o);
    return v;
}

// ---------------------------------------------------------------------------
// K0: zero accumulators (agg, degree histograms, colsum)
// ---------------------------------------------------------------------------
__global__ void k_zero(int n) {
    int i = blockIdx.x * blockDim.x + threadIdx.x;
    if (i < n * 5) g_agg[i] = 0.f;
    if (i < n) { g_degD[i] = 0; g_degR[i] = 0; }
    if (i < 64) g_colsum[i] = 0.f;
}

// ---------------------------------------------------------------------------
// K1: data->task scatter-add (GraphConv aggregation)
// ---------------------------------------------------------------------------
__global__ void k_dt(const float* __restrict__ data_x,
                     const int* __restrict__ src, const int* __restrict__ dst, int E) {
    int e = blockIdx.x * blockDim.x + threadIdx.x;
    if (e >= E) return;
    int s = __ldg(&src[e]);
    int d = __ldg(&dst[e]);
    const float* xr = data_x + s * 5;
    float* ar = g_agg + d * 5;
#pragma unroll
    for (int k = 0; k < 5; k++) atomicAdd(ar + k, __ldg(&xr[k]));
}

// ---------------------------------------------------------------------------
// K1b: degree histograms for both edge orientations
// ---------------------------------------------------------------------------
__global__ void k_hist(const int* __restrict__ tsrc, const int* __restrict__ tdst, int E) {
    int e = blockIdx.x * blockDim.x + threadIdx.x;
    if (e >= E) return;
    atomicAdd(&g_degD[__ldg(&tdst[e])], 1);
    atomicAdd(&g_degR[__ldg(&tsrc[e])], 1);
}

// ---------------------------------------------------------------------------
// Scan stage 1: per-block (1024 elems) exclusive scan of degree -> ptr (local)
// blockIdx.y selects D/R array
// ---------------------------------------------------------------------------
__global__ __launch_bounds__(256) void k_scan_blk(int n) {
    int arr = blockIdx.y;
    const int* deg = arr ? g_degR : g_degD;
    int* ptr = arr ? g_ptrR : g_ptrD;
    int* bsum = arr ? g_bsumR : g_bsumD;
    __shared__ int sh[256];
    int tid = threadIdx.x;
    int base = blockIdx.x * 1024;
    int v[4]; int s = 0;
#pragma unroll
    for (int j = 0; j < 4; j++) {
        int idx = base + tid * 4 + j;
        v[j] = (idx < n) ? deg[idx] : 0;
        s += v[j];
    }
    sh[tid] = s;
    __syncthreads();
#pragma unroll
    for (int d = 1; d < 256; d <<= 1) {
        int t = 0;
        if (tid >= d) t = sh[tid - d];
        __syncthreads();
        sh[tid] += t;
        __syncthreads();
    }
    int off = sh[tid] - s;  // exclusive prefix of this thread
#pragma unroll
    for (int j = 0; j < 4; j++) {
        int idx = base + tid * 4 + j;
        if (idx < n) ptr[idx] = off;
        off += v[j];
    }
    if (tid == 0) bsum[blockIdx.x] = sh[255];
}

// ---------------------------------------------------------------------------
// Scan stage 2: serial scan of block sums (nblk ~196, trivial)
// ---------------------------------------------------------------------------
__global__ void k_scan_top(int nblk) {
    int tid = threadIdx.x;
    if (tid == 0) {
        int a = 0;
        for (int i = 0; i < nblk; i++) { int t = g_bsumD[i]; g_bsumD[i] = a; a += t; }
    }
    if (tid == 1) {
        int a = 0;
        for (int i = 0; i < nblk; i++) { int t = g_bsumR[i]; g_bsumR[i] = a; a += t; }
    }
}

// ---------------------------------------------------------------------------
// Scan stage 3: add block offsets, init cursors, write ptr[n]=E
// ---------------------------------------------------------------------------
__global__ __launch_bounds__(256) void k_scan_fix(int n, int E) {
    int arr = blockIdx.y;
    int* ptr = arr ? g_ptrR : g_ptrD;
    int* cur = arr ? g_curR : g_curD;
    const int* bsum = arr ? g_bsumR : g_bsumD;
    int off = bsum[blockIdx.x];
    int base = blockIdx.x * 1024 + threadIdx.x * 4;
#pragma unroll
    for (int j = 0; j < 4; j++) {
        int idx = base + j;
        if (idx < n) { int v = ptr[idx] + off; ptr[idx] = v; cur[idx] = v; }
    }
    if (blockIdx.x == 0 && threadIdx.x == 0) ptr[n] = E;
}

// ---------------------------------------------------------------------------
// K1c: scatter edges into CSR (both orientations)
// ---------------------------------------------------------------------------
__global__ void k_scatter(const int* __restrict__ tsrc, const int* __restrict__ tdst, int E) {
    int e = blockIdx.x * blockDim.x + threadIdx.x;
    if (e >= E) return;
    int s = __ldg(&tsrc[e]);
    int d = __ldg(&tdst[e]);
    int p = atomicAdd(&g_curD[d], 1);
    g_srcD[p] = s;
    int q = atomicAdd(&g_curR[s], 1);
    g_srcR[q] = d;
}

// ---------------------------------------------------------------------------
// K2: fused = leaky(LN(agg @ Wrel + brel + tasks @ Wroot))   (warp per row)
// ---------------------------------------------------------------------------
__global__ void k_fused(const float* __restrict__ tasks_x,
                        const float* __restrict__ Wrel, const float* __restrict__ brel,
                        const float* __restrict__ Wroot,
                        const float* __restrict__ lng, const float* __restrict__ lnb,
                        int n) {
    int gt = blockIdx.x * blockDim.x + threadIdx.x;
    int r = gt >> 5, lane = gt & 31;
    if (r >= n) return;
    float p0 = __ldg(&brel[lane]);
    float p1 = __ldg(&brel[lane + 32]);
    const float* ar = g_agg + r * 5;
#pragma unroll
    for (int k = 0; k < 5; k++) {
        float a = ar[k];
        p0 += a * __ldg(&Wrel[k * 64 + lane]);
        p1 += a * __ldg(&Wrel[k * 64 + lane + 32]);
    }
    const float* tr = tasks_x + r * 12;
#pragma unroll
    for (int k = 0; k < 12; k++) {
        float t = __ldg(&tr[k]);
        p0 += t * __ldg(&Wroot[k * 64 + lane]);
        p1 += t * __ldg(&Wroot[k * 64 + lane + 32]);
    }
    float m = warp_sum(p0 + p1) * (1.f / 64.f);
    float d0 = p0 - m, d1 = p1 - m;
    float v = warp_sum(d0 * d0 + d1 * d1) * (1.f / 64.f);
    float inv = rsqrtf(v + 1e-5f);
    float y0 = leaky(d0 * inv * __ldg(&lng[lane])      + __ldg(&lnb[lane]));
    float y1 = leaky(d1 * inv * __ldg(&lng[lane + 32]) + __ldg(&lnb[lane + 32]));
    g_fused[r * 64 + lane]      = y0;
    g_fused[r * 64 + lane + 32] = y1;
}

// ---------------------------------------------------------------------------
// K3: B = fused @ W1b, C = fused @ (W1a - W1b) for one conv
// ---------------------------------------------------------------------------
__global__ __launch_bounds__(256) void k_gemm_bc(const float* __restrict__ W1,
                                                 int n, int conv) {
    extern __shared__ float sm[];
    float* Ws = sm;            // [64][128]
    float* Xs = sm + 8192;     // [128][65]
    int tid = threadIdx.x;
    int row0 = blockIdx.x * 128;

    for (int idx = tid; idx < 8192; idx += 256) {
        int k = idx >> 7, j = idx & 127;
        float wB = W1[(64 + k) * 64 + (j & 63)];
        Ws[idx] = (j < 64) ? wB : (W1[k * 64 + (j - 64)] - wB);
    }
#pragma unroll
    for (int it = 0; it < 8; it++) {
        int fi = tid + it * 256;
        int r = fi >> 4, c4 = (fi & 15) * 4;
        float4 v = make_float4(0.f, 0.f, 0.f, 0.f);
        int row = row0 + r;
        if (row < n) v = *reinterpret_cast<const float4*>(&g_fused[row * 64 + c4]);
        Xs[r * 65 + c4 + 0] = v.x;
        Xs[r * 65 + c4 + 1] = v.y;
        Xs[r * 65 + c4 + 2] = v.z;
        Xs[r * 65 + c4 + 3] = v.w;
    }
    __syncthreads();

    int tr = tid >> 4, tc = tid & 15;
    float acc[8][8];
#pragma unroll
    for (int i = 0; i < 8; i++)
#pragma unroll
        for (int j = 0; j < 8; j++) acc[i][j] = 0.f;

#pragma unroll 4
    for (int k = 0; k < 64; k++) {
        float4 w0 = *reinterpret_cast<float4*>(&Ws[k * 128 + tc * 8]);
        float4 w1 = *reinterpret_cast<float4*>(&Ws[k * 128 + tc * 8 + 4]);
#pragma unroll
        for (int i = 0; i < 8; i++) {
            float x = Xs[(tr * 8 + i) * 65 + k];
            acc[i][0] += x * w0.x; acc[i][1] += x * w0.y;
            acc[i][2] += x * w0.z; acc[i][3] += x * w0.w;
            acc[i][4] += x * w1.x; acc[i][5] += x * w1.y;
            acc[i][6] += x * w1.z; acc[i][7] += x * w1.w;
        }
    }

    float* Bo = conv ? g_Brev : g_Bdep;
    float* Co = conv ? g_Crev : g_Cdep;
    float* O = (tc < 8) ? Bo : Co;
    int cbase = (tc < 8) ? tc * 8 : (tc - 8) * 8;
#pragma unroll
    for (int i = 0; i < 8; i++) {
        int row = row0 + tr * 8 + i;
        if (row < n) {
            *reinterpret_cast<float4*>(&O[row * 64 + cbase]) =
                make_float4(acc[i][0], acc[i][1], acc[i][2], acc[i][3]);
            *reinterpret_cast<float4*>(&O[row * 64 + cbase + 4]) =
                make_float4(acc[i][4], acc[i][5], acc[i][6], acc[i][7]);
        }
    }
}

// ---------------------------------------------------------------------------
// K4: fused tail. Warp per node r:
//   S_dep = sum_{e in CSR_D[r]} leaky(C_dep[r] + B_dep[src] + b1d)   (registers)
//   dep = leaky(LN(S_dep @ W2d + degD*b2d));  rev likewise
//   tf = leaky([dep,rev] @ P + pb);  colsum += tf;  tf[0] -> out[64..127]
// Edge aggregation holds channels interleaved (lane owns 2l, 2l+1).
// ---------------------------------------------------------------------------
__global__ __launch_bounds__(256) void k_tail(
    const float* __restrict__ depb1, const float* __restrict__ depW2,
    const float* __restrict__ depb2,
    const float* __restrict__ depg,  const float* __restrict__ depb,
    const float* __restrict__ revb1, const float* __restrict__ revW2,
    const float* __restrict__ revb2,
    const float* __restrict__ revg,  const float* __restrict__ revb,
    const float* __restrict__ projW, const float* __restrict__ projb,
    float* __restrict__ out, int n) {
    extern __shared__ float sm[];
    float* W2d = sm;              // 4096
    float* W2r = sm + 4096;       // 4096
    float* P   = sm + 8192;       // 8192
    float* V   = sm + 16384;      // 576
    int tid = threadIdx.x;
    for (int i = tid; i < 4096; i += 256) { W2d[i] = depW2[i]; W2r[i] = revW2[i]; }
    for (int i = tid; i < 8192; i += 256) P[i] = projW[i];
    if (tid < 64) {
        V[tid]       = depb1[tid];
        V[64 + tid]  = revb1[tid];
        V[128 + tid] = depb2[tid];
        V[192 + tid] = revb2[tid];
        V[256 + tid] = depg[tid];
        V[320 + tid] = depb[tid];
        V[384 + tid] = revg[tid];
        V[448 + tid] = revb[tid];
        V[512 + tid] = projb[tid];
    }
    __syncthreads();

    int lane = tid & 31, wid = tid >> 5;
    float acc0 = 0.f, acc1 = 0.f;
    const unsigned FULL = 0xffffffffu;

    for (int r = blockIdx.x * 8 + wid; r < n; r += gridDim.x * 8) {
        // ================= dep branch =================
        int a0 = g_ptrD[r], a1 = g_ptrD[r + 1];
        float2 cv = *reinterpret_cast<const float2*>(&g_Cdep[r * 64 + 2 * lane]);
        float c0 = cv.x + V[2 * lane];
        float c1 = cv.y + V[2 * lane + 1];
        float s0 = 0.f, s1 = 0.f;
        for (int i0 = a0; i0 < a1; i0 += 32) {
            int cnt = min(32, a1 - i0);
            int mi = (lane < cnt) ? g_srcD[i0 + lane] : 0;
            for (int j = 0; j < cnt; j++) {
                int sIdx = __shfl_sync(FULL, mi, j);
                float2 b = *reinterpret_cast<const float2*>(&g_Bdep[sIdx * 64 + 2 * lane]);
                s0 += leaky(c0 + b.x);
                s1 += leaky(c1 + b.y);
            }
        }
        float dg = (float)(a1 - a0);
        float p0 = dg * V[128 + lane];
        float p1 = dg * V[160 + lane];
#pragma unroll
        for (int k = 0; k < 32; k++) {
            float aE = __shfl_sync(FULL, s0, k);  // channel 2k
            float aO = __shfl_sync(FULL, s1, k);  // channel 2k+1
            p0 += aE * W2d[(2 * k) * 64 + lane]      + aO * W2d[(2 * k + 1) * 64 + lane];
            p1 += aE * W2d[(2 * k) * 64 + 32 + lane] + aO * W2d[(2 * k + 1) * 64 + 32 + lane];
        }
        float m = warp_sum(p0 + p1) * (1.f / 64.f);
        float e0 = p0 - m, e1 = p1 - m;
        float v = warp_sum(e0 * e0 + e1 * e1) * (1.f / 64.f);
        float inv = rsqrtf(v + 1e-5f);
        float d0 = leaky(e0 * inv * V[256 + lane] + V[320 + lane]);
        float d1 = leaky(e1 * inv * V[288 + lane] + V[352 + lane]);

        // ================= rev branch =================
        a0 = g_ptrR[r]; a1 = g_ptrR[r + 1];
        cv = *reinterpret_cast<const float2*>(&g_Crev[r * 64 + 2 * lane]);
        c0 = cv.x + V[64 + 2 * lane];
        c1 = cv.y + V[64 + 2 * lane + 1];
        s0 = 0.f; s1 = 0.f;
        for (int i0 = a0; i0 < a1; i0 += 32) {
            int cnt = min(32, a1 - i0);
            int mi = (lane < cnt) ? g_srcR[i0 + lane] : 0;
            for (int j = 0; j < cnt; j++) {
                int sIdx = __shfl_sync(FULL, mi, j);
                float2 b = *reinterpret_cast<const float2*>(&g_Brev[sIdx * 64 + 2 * lane]);
                s0 += leaky(c0 + b.x);
                s1 += leaky(c1 + b.y);
            }
        }
        dg = (float)(a1 - a0);
        p0 = dg * V[192 + lane];
        p1 = dg * V[224 + lane];
#pragma unroll
        for (int k = 0; k < 32; k++) {
            float aE = __shfl_sync(FULL, s0, k);
            float aO = __shfl_sync(FULL, s1, k);
            p0 += aE * W2r[(2 * k) * 64 + lane]      + aO * W2r[(2 * k + 1) * 64 + lane];
            p1 += aE * W2r[(2 * k) * 64 + 32 + lane] + aO * W2r[(2 * k + 1) * 64 + 32 + lane];
        }
        m = warp_sum(p0 + p1) * (1.f / 64.f);
        e0 = p0 - m; e1 = p1 - m;
        v = warp_sum(e0 * e0 + e1 * e1) * (1.f / 64.f);
        inv = rsqrtf(v + 1e-5f);
        float r0 = leaky(e0 * inv * V[384 + lane] + V[448 + lane]);
        float r1 = leaky(e1 * inv * V[416 + lane] + V[480 + lane]);

        // ================= projection =================
        float q0 = V[512 + lane];
        float q1 = V[544 + lane];
#pragma unroll
        for (int k = 0; k < 32; k++) {
            float a = __shfl_sync(FULL, d0, k);           // channel k
            q0 += a * P[k * 64 + lane];
            q1 += a * P[k * 64 + 32 + lane];
        }
#pragma unroll
        for (int k = 0; k < 32; k++) {
            float a = __shfl_sync(FULL, d1, k);           // channel k+32
            q0 += a * P[(k + 32) * 64 + lane];
            q1 += a * P[(k + 32) * 64 + 32 + lane];
        }
#pragma unroll
        for (int k = 0; k < 32; k++) {
            float a = __shfl_sync(FULL, r0, k);           // channel 64+k
            q0 += a * P[(k + 64) * 64 + lane];
            q1 += a * P[(k + 64) * 64 + 32 + lane];
        }
#pragma unroll
        for (int k = 0; k < 32; k++) {
            float a = __shfl_sync(FULL, r1, k);           // channel 96+k
            q0 += a * P[(k + 96) * 64 + lane];
            q1 += a * P[(k + 96) * 64 + 32 + lane];
        }
        float t0 = leaky(q0), t1 = leaky(q1);
        acc0 += t0;
        acc1 += t1;
        if (r == 0) {
            out[64 + lane] = t0;
            out[96 + lane] = t1;
        }
    }
    atomicAdd(&g_colsum[lane], acc0);
    atomicAdd(&g_colsum[lane + 32], acc1);
}

// ---------------------------------------------------------------------------
// K5: finalize global state + device branch
// ---------------------------------------------------------------------------
__global__ void k_final(const int* __restrict__ counts,
                        const float* __restrict__ devx,
                        const float* __restrict__ timex,
                        const float* __restrict__ devW,
                        const float* __restrict__ devb,
                        float* __restrict__ out) {
    int tid = threadIdx.x;
    if (tid < 64) {
        int c = counts[0];
        if (c < 1) c = 1;
        out[tid] = g_colsum[tid] / (float)c;
    } else if (tid < 128) {
        int j = tid - 64;
        float p = devb[j];
#pragma unroll 8
        for (int k = 0; k < 96; k++) p += devx[k] * devW[k * 64 + j];
        p += (timex[0] * 1e-5f) * devW[96 * 64 + j];
        out[128 + j] = leaky(p);
    }
}

// ---------------------------------------------------------------------------
// Launch
// ---------------------------------------------------------------------------
extern "C" void kernel_launch(void* const* d_in, const int* in_sizes, int n_in,
                              void* d_out, int out_size) {
    const float* data_x    = (const float*)d_in[0];
    const float* tasks_x   = (const float*)d_in[1];
    const float* devices_x = (const float*)d_in[2];
    const float* time_x    = (const float*)d_in[3];
    const int*   dt_src    = (const int*)d_in[4];
    const int*   dt_dst    = (const int*)d_in[5];
    const int*   tt_src    = (const int*)d_in[6];
    const int*   tt_dst    = (const int*)d_in[7];
    const int*   counts    = (const int*)d_in[8];
    const float* gcWrel    = (const float*)d_in[9];
    const float* gcbrel    = (const float*)d_in[10];
    const float* gcWroot   = (const float*)d_in[11];
    const float* gclng     = (const float*)d_in[12];
    const float* gclnb     = (const float*)d_in[13];
    const float* depW1     = (const float*)d_in[14];
    const float* depb1     = (const float*)d_in[15];
    const float* depW2     = (const float*)d_in[16];
    const float* depb2     = (const float*)d_in[17];
    const float* deplng    = (const float*)d_in[18];
    const float* deplnb    = (const float*)d_in[19];
    const float* revW1     = (const float*)d_in[20];
    const float* revb1     = (const float*)d_in[21];
    const float* revW2     = (const float*)d_in[22];
    const float* revb2     = (const float*)d_in[23];
    const float* revlng    = (const float*)d_in[24];
    const float* revlnb    = (const float*)d_in[25];
    const float* devW      = (const float*)d_in[26];
    const float* devb      = (const float*)d_in[27];
    const float* projW     = (const float*)d_in[28];
    const float* projb     = (const float*)d_in[29];
    float* out = (float*)d_out;

    int n    = in_sizes[1] / 12;
    int e_dt = in_sizes[4];
    int e_tt = in_sizes[6];
    int nblk = (n + 1023) / 1024;

    cudaFuncSetAttribute(k_gemm_bc, cudaFuncAttributeMaxDynamicSharedMemorySize, 66048);
    cudaFuncSetAttribute(k_tail,    cudaFuncAttributeMaxDynamicSharedMemorySize, 67840);

    k_zero<<<(n * 5 + 255) / 256, 256>>>(n);
    k_dt<<<(e_dt + 255) / 256, 256>>>(data_x, dt_src, dt_dst, e_dt);
    k_hist<<<(e_tt + 255) / 256, 256>>>(tt_src, tt_dst, e_tt);

    dim3 sg(nblk, 2);
    k_scan_blk<<<sg, 256>>>(n);
    k_scan_top<<<1, 32>>>(nblk);
    k_scan_fix<<<sg, 256>>>(n, e_tt);
    k_scatter<<<(e_tt + 255) / 256, 256>>>(tt_src, tt_dst, e_tt);

    k_fused<<<(n * 32 + 255) / 256, 256>>>(tasks_x, gcWrel, gcbrel, gcWroot, gclng, gclnb, n);

    int gb = (n + 127) / 128;
    k_gemm_bc<<<gb, 256, 66048>>>(depW1, n, 0);
    k_gemm_bc<<<gb, 256, 66048>>>(revW1, n, 1);

    k_tail<<<1184, 256, 67840>>>(depb1, depW2, depb2, deplng, deplnb,
                                 revb1, revW2, revb2, revlng, revlnb,
                                 projW, projb, out, n);
    k_final<<<1, 128>>>(counts, devices_x, time_x, devW, devb, out);
}

// round 3
// speedup vs baseline: 1.5366x; 1.2414x over previous
#include <cuda_runtime.h>

#define NT_MAX 200000
#define ETT_MAX 1100000

// ---------------------------------------------------------------------------
// Scratch (__device__ globals — allocation-free rule)
// ---------------------------------------------------------------------------
__device__ float g_agg  [NT_MAX * 5];
__device__ float g_fused[NT_MAX * 64];
__device__ float g_Bdep [NT_MAX * 64];
__device__ float g_Cdep [NT_MAX * 64];
__device__ float g_Brev [NT_MAX * 64];
__device__ float g_Crev [NT_MAX * 64];
__device__ float g_Sdep [NT_MAX * 64];
__device__ float g_Srev [NT_MAX * 64];
__device__ int   g_degD [NT_MAX];
__device__ int   g_degR [NT_MAX];
__device__ int   g_ptrD [NT_MAX + 1];
__device__ int   g_ptrR [NT_MAX + 1];
__device__ int   g_curD [NT_MAX];
__device__ int   g_curR [NT_MAX];
__device__ int   g_srcD [ETT_MAX];
__device__ int   g_srcR [ETT_MAX];
__device__ int   g_bsumD[512];
__device__ int   g_bsumR[512];
__device__ float g_colsum[64];

__device__ __forceinline__ float leaky(float x) { return x > 0.f ? x : 0.01f * x; }

__device__ __forceinline__ float warp_sum(float v) {
#pragma unroll
    for (int o = 16; o > 0; o >>= 1) v += __shfl_xor_sync(0xffffffffu, v, o);
    return v;
}

// ---------------------------------------------------------------------------
// K0: zero accumulators
// ---------------------------------------------------------------------------
__global__ void k_zero(int n) {
    int i = blockIdx.x * blockDim.x + threadIdx.x;
    if (i < n * 5) g_agg[i] = 0.f;
    if (i < n) { g_degD[i] = 0; g_degR[i] = 0; }
    if (i < 64) g_colsum[i] = 0.f;
}

// ---------------------------------------------------------------------------
// K1: data->task scatter-add
// ---------------------------------------------------------------------------
__global__ void k_dt(const float* __restrict__ data_x,
                     const int* __restrict__ src, const int* __restrict__ dst, int E) {
    int e = blockIdx.x * blockDim.x + threadIdx.x;
    if (e >= E) return;
    int s = __ldg(&src[e]);
    int d = __ldg(&dst[e]);
    const float* xr = data_x + s * 5;
    float* ar = g_agg + d * 5;
#pragma unroll
    for (int k = 0; k < 5; k++) atomicAdd(ar + k, __ldg(&xr[k]));
}

// ---------------------------------------------------------------------------
// K1b: degree histograms
// ---------------------------------------------------------------------------
__global__ void k_hist(const int* __restrict__ tsrc, const int* __restrict__ tdst, int E) {
    int e = blockIdx.x * blockDim.x + threadIdx.x;
    if (e >= E) return;
    atomicAdd(&g_degD[__ldg(&tdst[e])], 1);
    atomicAdd(&g_degR[__ldg(&tsrc[e])], 1);
}

// ---------------------------------------------------------------------------
// Scan stage 1
// ---------------------------------------------------------------------------
__global__ __launch_bounds__(256) void k_scan_blk(int n) {
    int arr = blockIdx.y;
    const int* deg = arr ? g_degR : g_degD;
    int* ptr = arr ? g_ptrR : g_ptrD;
    int* bsum = arr ? g_bsumR : g_bsumD;
    __shared__ int sh[256];
    int tid = threadIdx.x;
    int base = blockIdx.x * 1024;
    int v[4]; int s = 0;
#pragma unroll
    for (int j = 0; j < 4; j++) {
        int idx = base + tid * 4 + j;
        v[j] = (idx < n) ? deg[idx] : 0;
        s += v[j];
    }
    sh[tid] = s;
    __syncthreads();
#pragma unroll
    for (int d = 1; d < 256; d <<= 1) {
        int t = 0;
        if (tid >= d) t = sh[tid - d];
        __syncthreads();
        sh[tid] += t;
        __syncthreads();
    }
    int off = sh[tid] - s;
#pragma unroll
    for (int j = 0; j < 4; j++) {
        int idx = base + tid * 4 + j;
        if (idx < n) ptr[idx] = off;
        off += v[j];
    }
    if (tid == 0) bsum[blockIdx.x] = sh[255];
}

// ---------------------------------------------------------------------------
// Scan stage 2
// ---------------------------------------------------------------------------
__global__ void k_scan_top(int nblk) {
    int tid = threadIdx.x;
    if (tid == 0) {
        int a = 0;
        for (int i = 0; i < nblk; i++) { int t = g_bsumD[i]; g_bsumD[i] = a; a += t; }
    }
    if (tid == 1) {
        int a = 0;
        for (int i = 0; i < nblk; i++) { int t = g_bsumR[i]; g_bsumR[i] = a; a += t; }
    }
}

// ---------------------------------------------------------------------------
// Scan stage 3
// ---------------------------------------------------------------------------
__global__ __launch_bounds__(256) void k_scan_fix(int n, int E) {
    int arr = blockIdx.y;
    int* ptr = arr ? g_ptrR : g_ptrD;
    int* cur = arr ? g_curR : g_curD;
    const int* bsum = arr ? g_bsumR : g_bsumD;
    int off = bsum[blockIdx.x];
    int base = blockIdx.x * 1024 + threadIdx.x * 4;
#pragma unroll
    for (int j = 0; j < 4; j++) {
        int idx = base + j;
        if (idx < n) { int v = ptr[idx] + off; ptr[idx] = v; cur[idx] = v; }
    }
    if (blockIdx.x == 0 && threadIdx.x == 0) ptr[n] = E;
}

// ---------------------------------------------------------------------------
// K1c: scatter edges into CSR
// ---------------------------------------------------------------------------
__global__ void k_scatter(const int* __restrict__ tsrc, const int* __restrict__ tdst, int E) {
    int e = blockIdx.x * blockDim.x + threadIdx.x;
    if (e >= E) return;
    int s = __ldg(&tsrc[e]);
    int d = __ldg(&tdst[e]);
    int p = atomicAdd(&g_curD[d], 1);
    g_srcD[p] = s;
    int q = atomicAdd(&g_curR[s], 1);
    g_srcR[q] = d;
}

// ---------------------------------------------------------------------------
// K2: fused = leaky(LN(agg @ Wrel + brel + tasks @ Wroot))   (warp per row)
// ---------------------------------------------------------------------------
__global__ void k_fused(const float* __restrict__ tasks_x,
                        const float* __restrict__ Wrel, const float* __restrict__ brel,
                        const float* __restrict__ Wroot,
                        const float* __restrict__ lng, const float* __restrict__ lnb,
                        int n) {
    int gt = blockIdx.x * blockDim.x + threadIdx.x;
    int r = gt >> 5, lane = gt & 31;
    if (r >= n) return;
    float p0 = __ldg(&brel[lane]);
    float p1 = __ldg(&brel[lane + 32]);
    const float* ar = g_agg + r * 5;
#pragma unroll
    for (int k = 0; k < 5; k++) {
        float a = ar[k];
        p0 += a * __ldg(&Wrel[k * 64 + lane]);
        p1 += a * __ldg(&Wrel[k * 64 + lane + 32]);
    }
    const float* tr = tasks_x + r * 12;
#pragma unroll
    for (int k = 0; k < 12; k++) {
        float t = __ldg(&tr[k]);
        p0 += t * __ldg(&Wroot[k * 64 + lane]);
        p1 += t * __ldg(&Wroot[k * 64 + lane + 32]);
    }
    float m = warp_sum(p0 + p1) * (1.f / 64.f);
    float d0 = p0 - m, d1 = p1 - m;
    float v = warp_sum(d0 * d0 + d1 * d1) * (1.f / 64.f);
    float inv = rsqrtf(v + 1e-5f);
    float y0 = leaky(d0 * inv * __ldg(&lng[lane])      + __ldg(&lnb[lane]));
    float y1 = leaky(d1 * inv * __ldg(&lng[lane + 32]) + __ldg(&lnb[lane + 32]));
    g_fused[r * 64 + lane]      = y0;
    g_fused[r * 64 + lane + 32] = y1;
}

// ---------------------------------------------------------------------------
// K3: B = fused @ W1b, C = fused @ (W1a - W1b) for one conv
// ---------------------------------------------------------------------------
__global__ __launch_bounds__(256) void k_gemm_bc(const float* __restrict__ W1,
                                                 int n, int conv) {
    extern __shared__ float sm[];
    float* Ws = sm;            // [64][128]
    float* Xs = sm + 8192;     // [128][65]
    int tid = threadIdx.x;
    int row0 = blockIdx.x * 128;

    for (int idx = tid; idx < 8192; idx += 256) {
        int k = idx >> 7, j = idx & 127;
        float wB = W1[(64 + k) * 64 + (j & 63)];
        Ws[idx] = (j < 64) ? wB : (W1[k * 64 + (j - 64)] - wB);
    }
#pragma unroll
    for (int it = 0; it < 8; it++) {
        int fi = tid + it * 256;
        int r = fi >> 4, c4 = (fi & 15) * 4;
        float4 v = make_float4(0.f, 0.f, 0.f, 0.f);
        int row = row0 + r;
        if (row < n) v = *reinterpret_cast<const float4*>(&g_fused[row * 64 + c4]);
        Xs[r * 65 + c4 + 0] = v.x;
        Xs[r * 65 + c4 + 1] = v.y;
        Xs[r * 65 + c4 + 2] = v.z;
        Xs[r * 65 + c4 + 3] = v.w;
    }
    __syncthreads();

    int tr = tid >> 4, tc = tid & 15;
    float acc[8][8];
#pragma unroll
    for (int i = 0; i < 8; i++)
#pragma unroll
        for (int j = 0; j < 8; j++) acc[i][j] = 0.f;

#pragma unroll 4
    for (int k = 0; k < 64; k++) {
        float4 w0 = *reinterpret_cast<float4*>(&Ws[k * 128 + tc * 8]);
        float4 w1 = *reinterpret_cast<float4*>(&Ws[k * 128 + tc * 8 + 4]);
#pragma unroll
        for (int i = 0; i < 8; i++) {
            float x = Xs[(tr * 8 + i) * 65 + k];
            acc[i][0] += x * w0.x; acc[i][1] += x * w0.y;
            acc[i][2] += x * w0.z; acc[i][3] += x * w0.w;
            acc[i][4] += x * w1.x; acc[i][5] += x * w1.y;
            acc[i][6] += x * w1.z; acc[i][7] += x * w1.w;
        }
    }

    float* Bo = conv ? g_Brev : g_Bdep;
    float* Co = conv ? g_Crev : g_Cdep;
    float* O = (tc < 8) ? Bo : Co;
    int cbase = (tc < 8) ? tc * 8 : (tc - 8) * 8;
#pragma unroll
    for (int i = 0; i < 8; i++) {
        int row = row0 + tr * 8 + i;
        if (row < n) {
            *reinterpret_cast<float4*>(&O[row * 64 + cbase]) =
                make_float4(acc[i][0], acc[i][1], acc[i][2], acc[i][3]);
            *reinterpret_cast<float4*>(&O[row * 64 + cbase + 4]) =
                make_float4(acc[i][4], acc[i][5], acc[i][6], acc[i][7]);
        }
    }
}

// ---------------------------------------------------------------------------
// K4: edge aggregation only. Warp per node:
//   S[r] = sum_{src in CSR[r]} leaky(C[r] + B[src] + b1)
// Lane owns channels (2l, 2l+1). Unrolled x4 for MLP.
// ---------------------------------------------------------------------------
__global__ __launch_bounds__(256) void k_agg(const float* __restrict__ b1,
                                             int n, int conv) {
    const int* ptr  = conv ? g_ptrR : g_ptrD;
    const int* srcA = conv ? g_srcR : g_srcD;
    const float* B  = conv ? g_Brev : g_Bdep;
    const float* C  = conv ? g_Crev : g_Cdep;
    float* S        = conv ? g_Srev : g_Sdep;
    const unsigned FULL = 0xffffffffu;
    int lane = threadIdx.x & 31, wid = threadIdx.x >> 5;
    int r = blockIdx.x * 8 + wid;
    if (r >= n) return;
    int a0 = ptr[r], a1 = ptr[r + 1];
    float2 cv = *reinterpret_cast<const float2*>(&C[r * 64 + 2 * lane]);
    float c0 = cv.x + __ldg(&b1[2 * lane]);
    float c1 = cv.y + __ldg(&b1[2 * lane + 1]);
    float s0 = 0.f, s1 = 0.f;
    for (int i0 = a0; i0 < a1; i0 += 32) {
        int cnt = min(32, a1 - i0);
        int mi = (lane < cnt) ? srcA[i0 + lane] : 0;
        int j = 0;
        for (; j + 4 <= cnt; j += 4) {
            int x0 = __shfl_sync(FULL, mi, j);
            int x1 = __shfl_sync(FULL, mi, j + 1);
            int x2 = __shfl_sync(FULL, mi, j + 2);
            int x3 = __shfl_sync(FULL, mi, j + 3);
            float2 b0 = *reinterpret_cast<const float2*>(&B[x0 * 64 + 2 * lane]);
            float2 b1v = *reinterpret_cast<const float2*>(&B[x1 * 64 + 2 * lane]);
            float2 b2 = *reinterpret_cast<const float2*>(&B[x2 * 64 + 2 * lane]);
            float2 b3 = *reinterpret_cast<const float2*>(&B[x3 * 64 + 2 * lane]);
            s0 += leaky(c0 + b0.x) + leaky(c0 + b1v.x) + leaky(c0 + b2.x) + leaky(c0 + b3.x);
            s1 += leaky(c1 + b0.y) + leaky(c1 + b1v.y) + leaky(c1 + b2.y) + leaky(c1 + b3.y);
        }
        for (; j < cnt; j++) {
            int xs = __shfl_sync(FULL, mi, j);
            float2 b = *reinterpret_cast<const float2*>(&B[xs * 64 + 2 * lane]);
            s0 += leaky(c0 + b.x);
            s1 += leaky(c1 + b.y);
        }
    }
    *reinterpret_cast<float2*>(&S[r * 64 + 2 * lane]) = make_float2(s0, s1);
}

// ---------------------------------------------------------------------------
// K5: tiled tail. Block = 128 rows.
//   Hd = S_dep@W2d + degD*b2d -> LN -> leaky -> Dp (smem)
//   Hr = S_rev@W2r + degR*b2r -> LN -> leaky -> Rv (smem)
//   tf = leaky([Dp,Rv]@P + pb) -> colsum (block-reduced), row0 -> out[64..127]
// smem: W 8192 | Xs 8704 | Dp 8704 | Rv 8704 | V 448 | colpart 1024 | deg 256
// ---------------------------------------------------------------------------
#define TS 68   // padded row stride (16B-aligned, conflict-shifting)

__global__ __launch_bounds__(256) void k_tail2(
    const float* __restrict__ depW2, const float* __restrict__ depb2,
    const float* __restrict__ depg,  const float* __restrict__ depb,
    const float* __restrict__ revW2, const float* __restrict__ revb2,
    const float* __restrict__ revg,  const float* __restrict__ revb,
    const float* __restrict__ projW, const float* __restrict__ projb,
    float* __restrict__ out, int n) {
    extern __shared__ float sm[];
    float* W  = sm;            // 8192
    float* Xs = sm + 8192;     // 128*TS = 8704
    float* Dp = sm + 16896;    // 8704
    float* Rv = sm + 25600;    // 8704
    float* V  = sm + 34304;    // 448
    float* CP = sm + 34752;    // 1024 colsum partials
    float* DG = sm + 35776;    // 256 (degD 128 + degR 128)

    int tid = threadIdx.x;
    int row0 = blockIdx.x * 128;
    int tr = tid >> 4, tc = tid & 15;     // 16x16: 8 rows x 4 cols each
    int lane = tid & 31, wid = tid >> 5;

    if (tid < 64) {
        V[tid]       = depb2[tid];
        V[64 + tid]  = revb2[tid];
        V[128 + tid] = depg[tid];
        V[192 + tid] = depb[tid];
        V[256 + tid] = revg[tid];
        V[320 + tid] = revb[tid];
        V[384 + tid] = projb[tid];
    }
    if (tid < 128) {
        int row = row0 + tid;
        DG[tid]       = (row < n) ? (float)(g_ptrD[row + 1] - g_ptrD[row]) : 0.f;
        DG[128 + tid] = (row < n) ? (float)(g_ptrR[row + 1] - g_ptrR[row]) : 0.f;
    }

    // ============ stage 1: dep ============
    for (int i = tid; i < 4096; i += 256) W[i] = depW2[i];
#pragma unroll
    for (int it = 0; it < 8; it++) {
        int fi = tid + it * 256;
        int r = fi >> 4, c4 = (fi & 15) * 4;
        float4 v = make_float4(0.f, 0.f, 0.f, 0.f);
        int row = row0 + r;
        if (row < n) v = *reinterpret_cast<const float4*>(&g_Sdep[row * 64 + c4]);
        *reinterpret_cast<float4*>(&Xs[r * TS + c4]) = v;
    }
    __syncthreads();

    {
        float acc[8][4];
#pragma unroll
        for (int i = 0; i < 8; i++)
#pragma unroll
            for (int j = 0; j < 4; j++) acc[i][j] = 0.f;
#pragma unroll 4
        for (int k = 0; k < 64; k++) {
            float4 w = *reinterpret_cast<float4*>(&W[k * 64 + tc * 4]);
#pragma unroll
            for (int i = 0; i < 8; i++) {
                float x = Xs[(tr * 8 + i) * TS + k];
                acc[i][0] += x * w.x; acc[i][1] += x * w.y;
                acc[i][2] += x * w.z; acc[i][3] += x * w.w;
            }
        }
        float4 b2 = *reinterpret_cast<const float4*>(&V[tc * 4]);
#pragma unroll
        for (int i = 0; i < 8; i++) {
            float dg = DG[tr * 8 + i];
            *reinterpret_cast<float4*>(&Dp[(tr * 8 + i) * TS + tc * 4]) =
                make_float4(acc[i][0] + dg * b2.x, acc[i][1] + dg * b2.y,
                            acc[i][2] + dg * b2.z, acc[i][3] + dg * b2.w);
        }
    }
    __syncthreads();

    // LN dep (warp per row, 16 rows/warp); concurrently load W2r + S_rev
#pragma unroll
    for (int t = 0; t < 16; t++) {
        int row = wid * 16 + t;
        float h0 = Dp[row * TS + lane];
        float h1 = Dp[row * TS + 32 + lane];
        float m = warp_sum(h0 + h1) * (1.f / 64.f);
        float e0 = h0 - m, e1 = h1 - m;
        float v = warp_sum(e0 * e0 + e1 * e1) * (1.f / 64.f);
        float inv = rsqrtf(v + 1e-5f);
        Dp[row * TS + lane]      = leaky(e0 * inv * V[128 + lane] + V[192 + lane]);
        Dp[row * TS + 32 + lane] = leaky(e1 * inv * V[160 + lane] + V[224 + lane]);
    }
    for (int i = tid; i < 4096; i += 256) W[i] = revW2[i];
#pragma unroll
    for (int it = 0; it < 8; it++) {
        int fi = tid + it * 256;
        int r = fi >> 4, c4 = (fi & 15) * 4;
        float4 v = make_float4(0.f, 0.f, 0.f, 0.f);
        int row = row0 + r;
        if (row < n) v = *reinterpret_cast<const float4*>(&g_Srev[row * 64 + c4]);
        *reinterpret_cast<float4*>(&Xs[r * TS + c4]) = v;
    }
    __syncthreads();

    // ============ stage 2: rev ============
    {
        float acc[8][4];
#pragma unroll
        for (int i = 0; i < 8; i++)
#pragma unroll
            for (int j = 0; j < 4; j++) acc[i][j] = 0.f;
#pragma unroll 4
        for (int k = 0; k < 64; k++) {
            float4 w = *reinterpret_cast<float4*>(&W[k * 64 + tc * 4]);
#pragma unroll
            for (int i = 0; i < 8; i++) {
                float x = Xs[(tr * 8 + i) * TS + k];
                acc[i][0] += x * w.x; acc[i][1] += x * w.y;
                acc[i][2] += x * w.z; acc[i][3] += x * w.w;
            }
        }
        float4 b2 = *reinterpret_cast<const float4*>(&V[64 + tc * 4]);
#pragma unroll
        for (int i = 0; i < 8; i++) {
            float dg = DG[128 + tr * 8 + i];
            *reinterpret_cast<float4*>(&Rv[(tr * 8 + i) * TS + tc * 4]) =
                make_float4(acc[i][0] + dg * b2.x, acc[i][1] + dg * b2.y,
                            acc[i][2] + dg * b2.z, acc[i][3] + dg * b2.w);
        }
    }
    __syncthreads();

    // LN rev; concurrently load P
#pragma unroll
    for (int t = 0; t < 16; t++) {
        int row = wid * 16 + t;
        float h0 = Rv[row * TS + lane];
        float h1 = Rv[row * TS + 32 + lane];
        float m = warp_sum(h0 + h1) * (1.f / 64.f);
        float e0 = h0 - m, e1 = h1 - m;
        float v = warp_sum(e0 * e0 + e1 * e1) * (1.f / 64.f);
        float inv = rsqrtf(v + 1e-5f);
        Rv[row * TS + lane]      = leaky(e0 * inv * V[256 + lane] + V[320 + lane]);
        Rv[row * TS + 32 + lane] = leaky(e1 * inv * V[288 + lane] + V[352 + lane]);
    }
    for (int i = tid; i < 8192; i += 256) W[i] = projW[i];
    __syncthreads();

    // ============ stage 3: proj + reduce ============
    {
        float acc[8][4];
#pragma unroll
        for (int i = 0; i < 8; i++)
#pragma unroll
            for (int j = 0; j < 4; j++) acc[i][j] = 0.f;
#pragma unroll 4
        for (int k = 0; k < 64; k++) {
            float4 w = *reinterpret_cast<float4*>(&W[k * 64 + tc * 4]);
#pragma unroll
            for (int i = 0; i < 8; i++) {
                float x = Dp[(tr * 8 + i) * TS + k];
                acc[i][0] += x * w.x; acc[i][1] += x * w.y;
                acc[i][2] += x * w.z; acc[i][3] += x * w.w;
            }
        }
#pragma unroll 4
        for (int k = 0; k < 64; k++) {
            float4 w = *reinterpret_cast<float4*>(&W[(k + 64) * 64 + tc * 4]);
#pragma unroll
            for (int i = 0; i < 8; i++) {
                float x = Rv[(tr * 8 + i) * TS + k];
                acc[i][0] += x * w.x; acc[i][1] += x * w.y;
                acc[i][2] += x * w.z; acc[i][3] += x * w.w;
            }
        }
        float4 pb = *reinterpret_cast<const float4*>(&V[384 + tc * 4]);
        float cs0 = 0.f, cs1 = 0.f, cs2 = 0.f, cs3 = 0.f;
#pragma unroll
        for (int i = 0; i < 8; i++) {
            int row = row0 + tr * 8 + i;
            float t0 = leaky(acc[i][0] + pb.x);
            float t1 = leaky(acc[i][1] + pb.y);
            float t2 = leaky(acc[i][2] + pb.z);
            float t3 = leaky(acc[i][3] + pb.w);
            if (row < n) { cs0 += t0; cs1 += t1; cs2 += t2; cs3 += t3; }
            if (row == 0) {
                out[64 + tc * 4 + 0] = t0;
                out[64 + tc * 4 + 1] = t1;
                out[64 + tc * 4 + 2] = t2;
                out[64 + tc * 4 + 3] = t3;
            }
        }
        *reinterpret_cast<float4*>(&CP[tr * 64 + tc * 4]) = make_float4(cs0, cs1, cs2, cs3);
    }
    __syncthreads();
    if (tid < 64) {
        float s = 0.f;
#pragma unroll
        for (int g = 0; g < 16; g++) s += CP[g * 64 + tid];
        atomicAdd(&g_colsum[tid], s);
    }
}

// ---------------------------------------------------------------------------
// K6: finalize global state + device branch
// ---------------------------------------------------------------------------
__global__ void k_final(const int* __restrict__ counts,
                        const float* __restrict__ devx,
                        const float* __restrict__ timex,
                        const float* __restrict__ devW,
                        const float* __restrict__ devb,
                        float* __restrict__ out) {
    int tid = threadIdx.x;
    if (tid < 64) {
        int c = counts[0];
        if (c < 1) c = 1;
        out[tid] = g_colsum[tid] / (float)c;
    } else if (tid < 128) {
        int j = tid - 64;
        float p = devb[j];
#pragma unroll 8
        for (int k = 0; k < 96; k++) p += devx[k] * devW[k * 64 + j];
        p += (timex[0] * 1e-5f) * devW[96 * 64 + j];
        out[128 + j] = leaky(p);
    }
}

// ---------------------------------------------------------------------------
// Launch
// ---------------------------------------------------------------------------
extern "C" void kernel_launch(void* const* d_in, const int* in_sizes, int n_in,
                              void* d_out, int out_size) {
    const float* data_x    = (const float*)d_in[0];
    const float* tasks_x   = (const float*)d_in[1];
    const float* devices_x = (const float*)d_in[2];
    const float* time_x    = (const float*)d_in[3];
    const int*   dt_src    = (const int*)d_in[4];
    const int*   dt_dst    = (const int*)d_in[5];
    const int*   tt_src    = (const int*)d_in[6];
    const int*   tt_dst    = (const int*)d_in[7];
    const int*   counts    = (const int*)d_in[8];
    const float* gcWrel    = (const float*)d_in[9];
    const float* gcbrel    = (const float*)d_in[10];
    const float* gcWroot   = (const float*)d_in[11];
    const float* gclng     = (const float*)d_in[12];
    const float* gclnb     = (const float*)d_in[13];
    const float* depW1     = (const float*)d_in[14];
    const float* depb1     = (const float*)d_in[15];
    const float* depW2     = (const float*)d_in[16];
    const float* depb2     = (const float*)d_in[17];
    const float* deplng    = (const float*)d_in[18];
    const float* deplnb    = (const float*)d_in[19];
    const float* revW1     = (const float*)d_in[20];
    const float* revb1     = (const float*)d_in[21];
    const float* revW2     = (const float*)d_in[22];
    const float* revb2     = (const float*)d_in[23];
    const float* revlng    = (const float*)d_in[24];
    const float* revlnb    = (const float*)d_in[25];
    const float* devW      = (const float*)d_in[26];
    const float* devb      = (const float*)d_in[27];
    const float* projW     = (const float*)d_in[28];
    const float* projb     = (const float*)d_in[29];
    float* out = (float*)d_out;

    int n    = in_sizes[1] / 12;
    int e_dt = in_sizes[4];
    int e_tt = in_sizes[6];
    int nblk = (n + 1023) / 1024;

    cudaFuncSetAttribute(k_gemm_bc, cudaFuncAttributeMaxDynamicSharedMemorySize, 66048);
    cudaFuncSetAttribute(k_tail2,   cudaFuncAttributeMaxDynamicSharedMemorySize, 36032 * 4);

    k_zero<<<(n * 5 + 255) / 256, 256>>>(n);
    k_dt<<<(e_dt + 255) / 256, 256>>>(data_x, dt_src, dt_dst, e_dt);
    k_hist<<<(e_tt + 255) / 256, 256>>>(tt_src, tt_dst, e_tt);

    dim3 sg(nblk, 2);
    k_scan_blk<<<sg, 256>>>(n);
    k_scan_top<<<1, 32>>>(nblk);
    k_scan_fix<<<sg, 256>>>(n, e_tt);
    k_scatter<<<(e_tt + 255) / 256, 256>>>(tt_src, tt_dst, e_tt);

    k_fused<<<(n * 32 + 255) / 256, 256>>>(tasks_x, gcWrel, gcbrel, gcWroot, gclng, gclnb, n);

    int gb = (n + 127) / 128;
    k_gemm_bc<<<gb, 256, 66048>>>(depW1, n, 0);
    k_gemm_bc<<<gb, 256, 66048>>>(revW1, n, 1);

    int ab = (n + 7) / 8;
    k_agg<<<ab, 256>>>(depb1, n, 0);
    k_agg<<<ab, 256>>>(revb1, n, 1);

    k_tail2<<<gb, 256, 36032 * 4>>>(depW2, depb2, deplng, deplnb,
                                    revW2, revb2, revlng, revlnb,
                                    projW, projb, out, n);
    k_final<<<1, 128>>>(counts, devices_x, time_x, devW, devb, out);
}